// round 1
// baseline (speedup 1.0000x reference)
#include <cuda_runtime.h>
#include <cstdint>

#define BB 64
#define HH 1024
#define SS 2048
#define LL 15

typedef unsigned long long ull;

// ---------------- scratch (static device globals; no allocation) ------------
__device__ float g_T[3 * BB * HH];        // tanh(x0), tanh(subj), tanh(obj)
__device__ float g_bcat[3 * HH];          // concat(b_cls,b_e1,b_e2)
__device__ float g_H3[BB * 3 * HH];       // concat(x0,e1,e2) after GEMM1
__device__ float g_h1[BB * HH];
__device__ float g_h2[BB * HH];
__device__ float g_P[24 * BB * 3 * HH];   // split-K partials (max 24*64*1024 == 8*64*3072)

// ---------------- f32x2 packed helpers --------------------------------------
__device__ __forceinline__ ull pack2(float x) {
    ull r; unsigned xi = __float_as_uint(x);
    asm("mov.b64 %0, {%1, %1};" : "=l"(r) : "r"(xi));
    return r;
}
__device__ __forceinline__ void ffma2(ull& acc, ull a, ull b) {
    asm("fma.rn.f32x2 %0, %1, %2, %3;" : "=l"(acc) : "l"(a), "l"(b), "l"(acc));
}
__device__ __forceinline__ float2 unpack2(ull v) {
    unsigned lo, hi;
    asm("mov.b64 {%0, %1}, %2;" : "=r"(lo), "=r"(hi) : "l"(v));
    float2 f; f.x = __uint_as_float(lo); f.y = __uint_as_float(hi);
    return f;
}

// ---------------- prep: span means + tanh + bias concat ---------------------
__global__ void prep_kernel(const float* __restrict__ x,
                            const int* __restrict__ eidx,
                            const float* __restrict__ b_cls,
                            const float* __restrict__ b_e1,
                            const float* __restrict__ b_e2) {
    int b = blockIdx.x;
    int tid = threadIdx.x;  // 256

    int gidx = b * 256 + tid;
    if (gidx < HH)            g_bcat[gidx] = b_cls[gidx];
    else if (gidx < 2 * HH)   g_bcat[gidx] = b_e1[gidx - HH];
    else if (gidx < 3 * HH)   g_bcat[gidx] = b_e2[gidx - 2 * HH];

    int s1 = eidx[b * 4 + 0], e1 = eidx[b * 4 + 1];
    int s2 = eidx[b * 4 + 2], e2 = eidx[b * 4 + 3];
    float c1 = 1.0f / (float)max(e1 - s1, 1);
    float c2 = 1.0f / (float)max(e2 - s2, 1);
    const float* xb = x + (size_t)b * SS * HH;

    for (int h = tid; h < HH; h += 256) {
        float t0 = tanhf(xb[h]);
        float a1 = 0.f;
        for (int p = s1; p < e1; ++p) a1 += xb[(size_t)p * HH + h];
        float a2 = 0.f;
        for (int p = s2; p < e2; ++p) a2 += xb[(size_t)p * HH + h];
        g_T[0 * BB * HH + b * HH + h] = t0;
        g_T[1 * BB * HH + b * HH + h] = tanhf(a1 * c1);
        g_T[2 * BB * HH + b * HH + h] = tanhf(a2 * c2);
    }
}

// ---------------- split-K skinny GEMM (M=64) ---------------------------------
// Y_partial[ks][b][n] = sum_{k in chunk} X[b][k] * W[k][n]
// Block tile: 64(b) x 128(n), BK=16. 128 threads, thread tile 8b x 8n (f32x2 over n pairs).
#define BKK 16
#define BNN 128
__global__ __launch_bounds__(128)
void gemm_split(int xsel,                    // 0: g_T, 1: g_H3, 2: g_h1
                int ldx,
                const float* __restrict__ W0,
                const float* __restrict__ W1p,
                const float* __restrict__ W2p,
                int segn,                    // 0: single weight; else columns/segment
                int Kd, int Ntot, int ldw, int kchunk) {
    const float* X = (xsel == 0) ? g_T : (xsel == 1) ? g_H3 : g_h1;
    int n0 = blockIdx.x * BNN;
    const float* W = W0;
    int ncol = n0;
    if (segn) {
        int which = n0 / segn;
        W = (which == 0) ? W0 : (which == 1 ? W1p : W2p);
        ncol = n0 - which * segn;
        X += (size_t)which * BB * Kd;
    }
    int kbeg = blockIdx.y * kchunk;
    int kend = min(kbeg + kchunk, Kd);

    __shared__ float Xs[BKK][BB];
    __shared__ float Ws[BKK][BNN];

    int tid = threadIdx.x;
    int tn = tid & 15;   // n group 0..15
    int tb = tid >> 4;   // b group 0..7

    ull acc[8][4];
#pragma unroll
    for (int i = 0; i < 8; i++)
#pragma unroll
        for (int j = 0; j < 4; j++) acc[i][j] = 0ULL;

    for (int k0 = kbeg; k0 < kend; k0 += BKK) {
        // --- stage X tile: Xs[kk][b] ---
        {
            int bbi = tid >> 1;
            int q = (tid & 1) * 8;
            const float* xp = X + (size_t)bbi * ldx + k0 + q;
            float4 v0 = *(const float4*)(xp);
            float4 v1 = *(const float4*)(xp + 4);
            Xs[q + 0][bbi] = v0.x; Xs[q + 1][bbi] = v0.y;
            Xs[q + 2][bbi] = v0.z; Xs[q + 3][bbi] = v0.w;
            Xs[q + 4][bbi] = v1.x; Xs[q + 5][bbi] = v1.y;
            Xs[q + 6][bbi] = v1.z; Xs[q + 7][bbi] = v1.w;
        }
        // --- stage W tile: Ws[kk][n] ---
        {
            int r = tid >> 5;              // 0..3
            int c = (tid & 31) * 4;        // 0..124
#pragma unroll
            for (int rr = 0; rr < BKK; rr += 4) {
                float4 wv = *(const float4*)(W + (size_t)(k0 + rr + r) * ldw + ncol + c);
                *(float4*)&Ws[rr + r][c] = wv;
            }
        }
        __syncthreads();

#pragma unroll
        for (int kk = 0; kk < BKK; ++kk) {
            float4 xa = *(const float4*)&Xs[kk][tb * 8];
            float4 xc = *(const float4*)&Xs[kk][tb * 8 + 4];
            ull x2[8];
            x2[0] = pack2(xa.x); x2[1] = pack2(xa.y);
            x2[2] = pack2(xa.z); x2[3] = pack2(xa.w);
            x2[4] = pack2(xc.x); x2[5] = pack2(xc.y);
            x2[6] = pack2(xc.z); x2[7] = pack2(xc.w);
            ulonglong2 wv0 = *(const ulonglong2*)&Ws[kk][tn * 8];
            ulonglong2 wv1 = *(const ulonglong2*)&Ws[kk][tn * 8 + 4];
            ull w2[4]; w2[0] = wv0.x; w2[1] = wv0.y; w2[2] = wv1.x; w2[3] = wv1.y;
#pragma unroll
            for (int i = 0; i < 8; i++)
#pragma unroll
                for (int j = 0; j < 4; j++) ffma2(acc[i][j], x2[i], w2[j]);
        }
        __syncthreads();
    }

    // --- write partials ---
#pragma unroll
    for (int i = 0; i < 8; i++) {
        int b = tb * 8 + i;
        float* row = g_P + ((size_t)blockIdx.y * BB + b) * Ntot + n0 + tn * 8;
        float2 f0 = unpack2(acc[i][0]), f1 = unpack2(acc[i][1]);
        float2 f2 = unpack2(acc[i][2]), f3 = unpack2(acc[i][3]);
        float4 o0 = make_float4(f0.x, f0.y, f1.x, f1.y);
        float4 o1 = make_float4(f2.x, f2.y, f3.x, f3.y);
        *(float4*)row = o0;
        *(float4*)(row + 4) = o1;
    }
}

// ---------------- reduce split-K partials + bias -----------------------------
__global__ void reduce_bias(const float* __restrict__ bias,  // nullptr -> g_bcat
                            int ysel,                        // 0: g_H3, 1: g_h1, 2: g_h2
                            int Ntot, int ks) {
    float* Y = (ysel == 0) ? g_H3 : (ysel == 1) ? g_h1 : g_h2;
    const float* bp = bias ? bias : g_bcat;
    int idx = blockIdx.x * 256 + threadIdx.x;     // float4 index over B*Ntot
    int total = BB * Ntot / 4;
    if (idx >= total) return;
    float4 s = ((const float4*)g_P)[idx];
    for (int q = 1; q < ks; q++) {
        float4 v = ((const float4*)g_P)[(size_t)q * total + idx];
        s.x += v.x; s.y += v.y; s.z += v.z; s.w += v.w;
    }
    int n = (idx * 4) % Ntot;
    float4 bv = *(const float4*)(bp + n);
    s.x += bv.x; s.y += bv.y; s.z += bv.z; s.w += bv.w;
    ((float4*)Y)[idx] = s;
}

// ---------------- tiny output GEMM: [64,1024] @ [1024,15] --------------------
__global__ void out_gemm(const float* __restrict__ Wout,
                         const float* __restrict__ bout,
                         float* __restrict__ out) {
    int n = blockIdx.x;   // 0..14
    int b = blockIdx.y;   // 0..63
    float s = 0.f;
    for (int k = threadIdx.x; k < HH; k += 128)
        s += g_h2[b * HH + k] * Wout[k * LL + n];
    __shared__ float red[4];
#pragma unroll
    for (int o = 16; o; o >>= 1) s += __shfl_down_sync(0xffffffffu, s, o);
    if ((threadIdx.x & 31) == 0) red[threadIdx.x >> 5] = s;
    __syncthreads();
    if (threadIdx.x == 0)
        out[b * LL + n] = red[0] + red[1] + red[2] + red[3] + bout[n];
}

// ---------------- launch ------------------------------------------------------
extern "C" void kernel_launch(void* const* d_in, const int* in_sizes, int n_in,
                              void* d_out, int out_size) {
    const float* x      = (const float*)d_in[0];
    const int*   eidx   = (const int*)d_in[1];
    const float* W_cls  = (const float*)d_in[2];
    const float* b_cls  = (const float*)d_in[3];
    const float* W_e1   = (const float*)d_in[4];
    const float* b_e1   = (const float*)d_in[5];
    const float* W_e2   = (const float*)d_in[6];
    const float* b_e2   = (const float*)d_in[7];
    const float* W1     = (const float*)d_in[8];
    const float* b1     = (const float*)d_in[9];
    const float* W2     = (const float*)d_in[10];
    const float* b2     = (const float*)d_in[11];
    const float* Wout   = (const float*)d_in[12];
    const float* bout   = (const float*)d_in[13];
    float* out = (float*)d_out;

    // 1) span means + tanh + bias concat
    prep_kernel<<<BB, 256>>>(x, eidx, b_cls, b_e1, b_e2);

    // 2) GEMM1: [64,1024] x 3 block-diag weights -> partials (Ntot=3072, ks=8)
    gemm_split<<<dim3(3 * HH / BNN, 8), 128>>>(0, HH, W_cls, W_e1, W_e2,
                                               HH, HH, 3 * HH, HH, 128);
    reduce_bias<<<(BB * 3 * HH / 4 + 255) / 256, 256>>>(nullptr, 0, 3 * HH, 8);

    // 3) GEMM2: [64,3072] @ W1[3072,1024] (ks=24)
    gemm_split<<<dim3(HH / BNN, 24), 128>>>(1, 3 * HH, W1, nullptr, nullptr,
                                            0, 3 * HH, HH, HH, 128);
    reduce_bias<<<(BB * HH / 4 + 255) / 256, 256>>>(b1, 1, HH, 24);

    // 4) GEMM3: [64,1024] @ W2[1024,1024] (ks=16, kchunk=64)
    gemm_split<<<dim3(HH / BNN, 16), 128>>>(2, HH, W2, nullptr, nullptr,
                                            0, HH, HH, HH, 64);
    reduce_bias<<<(BB * HH / 4 + 255) / 256, 256>>>(b2, 2, HH, 16);

    // 5) output projection
    out_gemm<<<dim3(LL, BB), 128>>>(Wout, bout, out);

    (void)in_sizes; (void)n_in; (void)out_size;
}

// round 2
// speedup vs baseline: 1.2036x; 1.2036x over previous
#include <cuda_runtime.h>
#include <cstdint>

#define BB 64
#define HH 1024
#define SS 2048
#define LL 15
#define BKK 16
#define BNN 128

typedef unsigned long long ull;

// ---------------- scratch (static device globals; no allocation) ------------
// Activations stored K-major: A[k*BB + b]
__device__ float g_T[3 * HH * BB];      // tanh inputs, 3 segments of [HH][BB]
__device__ float g_bcat[3 * HH];        // concat(b_cls,b_e1,b_e2)
__device__ float g_H3[3 * HH * BB];     // GEMM1 output [3H][B]
__device__ float g_h1[HH * BB];         // GEMM2 output [H][B]
__device__ float g_h2[HH * BB];         // GEMM3 output [H][B]
__device__ float g_h2b[BB * HH];        // b-major copy of h2 for out gemm
__device__ float g_P[16 * 3 * HH * BB]; // split-K partials [q][n][b] (max 12.6MB)

// ---------------- f32x2 packed helpers --------------------------------------
__device__ __forceinline__ ull pack2(float x) {
    ull r; unsigned xi = __float_as_uint(x);
    asm("mov.b64 %0, {%1, %1};" : "=l"(r) : "r"(xi));
    return r;
}
__device__ __forceinline__ void ffma2(ull& acc, ull a, ull b) {
    asm("fma.rn.f32x2 %0, %1, %2, %3;" : "=l"(acc) : "l"(a), "l"(b), "l"(acc));
}
__device__ __forceinline__ float2 unpack2(ull v) {
    unsigned lo, hi;
    asm("mov.b64 {%0, %1}, %2;" : "=r"(lo), "=r"(hi) : "l"(v));
    float2 f; f.x = __uint_as_float(lo); f.y = __uint_as_float(hi);
    return f;
}

// ---------------- cp.async helpers ------------------------------------------
__device__ __forceinline__ void cp16(void* s, const void* g) {
    unsigned ss = (unsigned)__cvta_generic_to_shared(s);
    asm volatile("cp.async.cg.shared.global [%0], [%1], 16;" :: "r"(ss), "l"(g));
}
#define CP_COMMIT asm volatile("cp.async.commit_group;")
#define CP_WAIT1  asm volatile("cp.async.wait_group 1;")
#define CP_WAIT0  asm volatile("cp.async.wait_group 0;")

// ---------------- prep: span means + tanh + bias concat ---------------------
__global__ void prep_kernel(const float* __restrict__ x,
                            const int* __restrict__ eidx,
                            const float* __restrict__ b_cls,
                            const float* __restrict__ b_e1,
                            const float* __restrict__ b_e2) {
    int b = blockIdx.x;
    int tid = threadIdx.x;  // 256
    int h = blockIdx.y * 256 + tid;

    if (blockIdx.y == 0 && b < 12) {
        int gidx = b * 256 + tid;
        if (gidx < HH)          g_bcat[gidx] = b_cls[gidx];
        else if (gidx < 2 * HH) g_bcat[gidx] = b_e1[gidx - HH];
        else                    g_bcat[gidx] = b_e2[gidx - 2 * HH];
    }

    int s1 = eidx[b * 4 + 0], e1 = eidx[b * 4 + 1];
    int s2 = eidx[b * 4 + 2], e2 = eidx[b * 4 + 3];
    float c1 = 1.0f / (float)max(e1 - s1, 1);
    float c2 = 1.0f / (float)max(e2 - s2, 1);
    const float* xb = x + (size_t)b * SS * HH;

    float t0 = tanhf(xb[h]);
    float a1 = 0.f;
    for (int p = s1; p < e1; ++p) a1 += xb[(size_t)p * HH + h];
    float a2 = 0.f;
    for (int p = s2; p < e2; ++p) a2 += xb[(size_t)p * HH + h];
    // transposed (K-major) writes
    g_T[(size_t)(0 * HH + h) * BB + b] = t0;
    g_T[(size_t)(1 * HH + h) * BB + b] = tanhf(a1 * c1);
    g_T[(size_t)(2 * HH + h) * BB + b] = tanhf(a2 * c2);
}

// ---------------- split-K skinny GEMM (M=64), double-buffered cp.async -------
// X is K-major [K][64]. P[q][n][b] partial output.
// Block tile: 64(b) x 128(n), BK=16. 128 threads, thread tile 8b x 8n (f32x2 pairs over n).
__global__ __launch_bounds__(128)
void gemm_split(int xsel,                    // 0: g_T, 1: g_H3, 2: g_h1
                const float* __restrict__ W0,
                const float* __restrict__ We1,
                const float* __restrict__ We2,
                int seg,                     // 0: single weight; else cols/segment
                int Ntot, int ldw, int kchunk) {
    const float* X = (xsel == 0) ? g_T : (xsel == 1) ? g_H3 : g_h1;
    int n0 = blockIdx.x * BNN;
    const float* W = W0;
    int ncol = n0;
    if (seg) {
        int which = n0 / seg;
        W = (which == 0) ? W0 : (which == 1 ? We1 : We2);
        ncol = n0 - which * seg;
        X += (size_t)which * HH * BB;   // segment rows
    }
    int kbeg = blockIdx.y * kchunk;
    int ntiles = kchunk / BKK;

    __shared__ float Xs[2][BKK][BB];    // 2 x 4KB
    __shared__ float Ws[2][BKK][BNN];   // 2 x 8KB

    int tid = threadIdx.x;
    int tn = tid & 15;   // n group 0..15 (8 cols each)
    int tb = tid >> 4;   // b group 0..7 (8 rows each)

    ull acc[8][4];
#pragma unroll
    for (int i = 0; i < 8; i++)
#pragma unroll
        for (int j = 0; j < 4; j++) acc[i][j] = 0ULL;

    // --- staging lambda: X tile 4KB (2 cp16/thread), W tile 8KB (4 cp16/thread)
    auto stage = [&](int s, int k0) {
#pragma unroll
        for (int i = 0; i < 2; i++) {
            int p = tid + 128 * i;
            int r = p >> 4, c = (p & 15) * 4;
            cp16(&Xs[s][r][c], X + (size_t)(k0 + r) * BB + c);
        }
#pragma unroll
        for (int i = 0; i < 4; i++) {
            int p = tid + 128 * i;
            int r = p >> 5, c = (p & 31) * 4;
            cp16(&Ws[s][r][c], W + (size_t)(k0 + r) * ldw + ncol + c);
        }
    };

    stage(0, kbeg);
    CP_COMMIT;

    for (int t = 0; t < ntiles; t++) {
        int s = t & 1;
        if (t + 1 < ntiles) {
            stage(s ^ 1, kbeg + (t + 1) * BKK);
            CP_COMMIT;
            CP_WAIT1;
        } else {
            CP_WAIT0;
        }
        __syncthreads();

#pragma unroll
        for (int kk = 0; kk < BKK; ++kk) {
            float4 xa = *(const float4*)&Xs[s][kk][tb * 8];
            float4 xc = *(const float4*)&Xs[s][kk][tb * 8 + 4];
            ull x2[8];
            x2[0] = pack2(xa.x); x2[1] = pack2(xa.y);
            x2[2] = pack2(xa.z); x2[3] = pack2(xa.w);
            x2[4] = pack2(xc.x); x2[5] = pack2(xc.y);
            x2[6] = pack2(xc.z); x2[7] = pack2(xc.w);
            ulonglong2 wv0 = *(const ulonglong2*)&Ws[s][kk][tn * 8];
            ulonglong2 wv1 = *(const ulonglong2*)&Ws[s][kk][tn * 8 + 4];
            ull w2[4]; w2[0] = wv0.x; w2[1] = wv0.y; w2[2] = wv1.x; w2[3] = wv1.y;
#pragma unroll
            for (int i = 0; i < 8; i++)
#pragma unroll
                for (int j = 0; j < 4; j++) ffma2(acc[i][j], x2[i], w2[j]);
        }
        __syncthreads();
    }

    // --- write partials transposed: P[(q*Ntot + n)*64 + b]
    float* base = g_P + ((size_t)blockIdx.y * Ntot + n0 + tn * 8) * BB + tb * 8;
#pragma unroll
    for (int j = 0; j < 4; j++) {
        float2 f0 = unpack2(acc[0][j]), f1 = unpack2(acc[1][j]);
        float2 f2 = unpack2(acc[2][j]), f3 = unpack2(acc[3][j]);
        float2 f4 = unpack2(acc[4][j]), f5 = unpack2(acc[5][j]);
        float2 f6 = unpack2(acc[6][j]), f7 = unpack2(acc[7][j]);
        float* r0 = base + (size_t)(2 * j) * BB;
        *(float4*)r0       = make_float4(f0.x, f1.x, f2.x, f3.x);
        *(float4*)(r0 + 4) = make_float4(f4.x, f5.x, f6.x, f7.x);
        float* r1 = base + (size_t)(2 * j + 1) * BB;
        *(float4*)r1       = make_float4(f0.y, f1.y, f2.y, f3.y);
        *(float4*)(r1 + 4) = make_float4(f4.y, f5.y, f6.y, f7.y);
    }
}

// ---------------- reduce split-K partials + bias (layout [n][b]) -------------
__global__ void reduce_bias(const float* __restrict__ bias,  // nullptr -> g_bcat
                            int ysel,                        // 0:g_H3 1:g_h1 2:g_h2
                            int Ntot, int ks) {
    float* Y = (ysel == 0) ? g_H3 : (ysel == 1) ? g_h1 : g_h2;
    const float* bp = bias ? bias : g_bcat;
    int idx = blockIdx.x * 256 + threadIdx.x;     // float4 index over Ntot*BB
    int total = Ntot * BB / 4;
    if (idx >= total) return;
    float4 s = ((const float4*)g_P)[idx];
    for (int q = 1; q < ks; q++) {
        float4 v = ((const float4*)g_P)[(size_t)q * total + idx];
        s.x += v.x; s.y += v.y; s.z += v.z; s.w += v.w;
    }
    int n = idx >> 4;            // 16 float4 per n row (BB=64)
    float bv = bp[n];
    s.x += bv; s.y += bv; s.z += bv; s.w += bv;
    ((float4*)Y)[idx] = s;
    if (ysel == 2) {
        int b = (idx & 15) * 4;
        g_h2b[(size_t)(b + 0) * HH + n] = s.x;
        g_h2b[(size_t)(b + 1) * HH + n] = s.y;
        g_h2b[(size_t)(b + 2) * HH + n] = s.z;
        g_h2b[(size_t)(b + 3) * HH + n] = s.w;
    }
}

// ---------------- tiny output GEMM: [64,1024] @ [1024,15] --------------------
__global__ void out_gemm(const float* __restrict__ Wout,
                         const float* __restrict__ bout,
                         float* __restrict__ out) {
    int n = blockIdx.x;   // 0..14
    int b = blockIdx.y;   // 0..63
    float s = 0.f;
    for (int k = threadIdx.x; k < HH; k += 128)
        s += g_h2b[(size_t)b * HH + k] * Wout[(size_t)k * LL + n];
    __shared__ float red[4];
#pragma unroll
    for (int o = 16; o; o >>= 1) s += __shfl_down_sync(0xffffffffu, s, o);
    if ((threadIdx.x & 31) == 0) red[threadIdx.x >> 5] = s;
    __syncthreads();
    if (threadIdx.x == 0)
        out[b * LL + n] = red[0] + red[1] + red[2] + red[3] + bout[n];
}

// ---------------- launch ------------------------------------------------------
extern "C" void kernel_launch(void* const* d_in, const int* in_sizes, int n_in,
                              void* d_out, int out_size) {
    const float* x      = (const float*)d_in[0];
    const int*   eidx   = (const int*)d_in[1];
    const float* W_cls  = (const float*)d_in[2];
    const float* b_cls  = (const float*)d_in[3];
    const float* W_e1   = (const float*)d_in[4];
    const float* b_e1   = (const float*)d_in[5];
    const float* W_e2   = (const float*)d_in[6];
    const float* b_e2   = (const float*)d_in[7];
    const float* W1     = (const float*)d_in[8];
    const float* b1     = (const float*)d_in[9];
    const float* W2     = (const float*)d_in[10];
    const float* b2     = (const float*)d_in[11];
    const float* Wout   = (const float*)d_in[12];
    const float* bout   = (const float*)d_in[13];
    float* out = (float*)d_out;

    // 1) span means + tanh + bias concat (grid 64 x 4, 256 h per block)
    prep_kernel<<<dim3(BB, HH / 256), 256>>>(x, eidx, b_cls, b_e1, b_e2);

    // 2) GEMM1: [64,1024] x block-diag(W_cls,W_e1,W_e2) -> [3072][64]
    //    grid 24 x 16 = 384 CTAs, kchunk 64
    gemm_split<<<dim3(3 * HH / BNN, 16), 128>>>(0, W_cls, W_e1, W_e2,
                                                HH, 3 * HH, HH, 64);
    reduce_bias<<<(3 * HH * BB / 4) / 256, 256>>>(nullptr, 0, 3 * HH, 16);

    // 3) GEMM2: [64,3072] @ W1[3072,1024], grid 8 x 24 = 192 CTAs, kchunk 128
    gemm_split<<<dim3(HH / BNN, 24), 128>>>(1, W1, nullptr, nullptr,
                                            0, HH, HH, 128);
    reduce_bias<<<(HH * BB / 4) / 256, 256>>>(b1, 1, HH, 24);

    // 4) GEMM3: [64,1024] @ W2[1024,1024], grid 8 x 16 = 128 CTAs, kchunk 64
    gemm_split<<<dim3(HH / BNN, 16), 128>>>(2, W2, nullptr, nullptr,
                                            0, HH, HH, 64);
    reduce_bias<<<(HH * BB / 4) / 256, 256>>>(b2, 2, HH, 16);

    // 5) output projection
    out_gemm<<<dim3(LL, BB), 128>>>(Wout, bout, out);

    (void)in_sizes; (void)n_in; (void)out_size;
}